// round 2
// baseline (speedup 1.0000x reference)
#include <cuda_runtime.h>
#include <cuda_bf16.h>

__global__ __launch_bounds__(256) void rinter_area_kernel2(
    const float4* __restrict__ pts,      // N rows * 4 float4 each
    const int* __restrict__ num_of_inter,
    float* __restrict__ out,
    int n)
{
    int i0 = (blockIdx.x * blockDim.x + threadIdx.x) * 2;
    if (i0 >= n) return;

    // Front-batch all loads: 8x LDG.128 + 1x LDG.64 worth of traffic (2 ints).
    const float4* r0 = pts + (size_t)i0 * 4;
    const float4* r1 = r0 + 4;

    float4 a0 = __ldcs(r0 + 0);
    float4 b0 = __ldcs(r0 + 1);
    float4 c0 = __ldcs(r0 + 2);
    float4 d0 = __ldcs(r0 + 3);
    float4 a1 = __ldcs(r1 + 0);
    float4 b1 = __ldcs(r1 + 1);
    float4 c1 = __ldcs(r1 + 2);
    float4 d1 = __ldcs(r1 + 3);
    // two ints as a single 64-bit load (i0 is even so 8B-aligned)
    int2 ni = __ldcs((const int2*)(num_of_inter + i0));

    float2 res;

    {
        float px[8] = {a0.x, a0.z, b0.x, b0.z, c0.x, c0.z, d0.x, d0.z};
        float py[8] = {a0.y, a0.w, b0.y, b0.w, c0.y, c0.w, d0.y, d0.w};
        int ntri = ni.x - 2;
        float sum = 0.0f;
        #pragma unroll
        for (int t = 0; t < 6; t++) {
            float cross = (px[0] - px[2 + t]) * (py[1 + t] - py[2 + t])
                        - (py[0] - py[2 + t]) * (px[1 + t] - px[2 + t]);
            sum += (t < ntri) ? fabsf(cross) * 0.5f : 0.0f;
        }
        res.x = sum;
    }
    {
        float px[8] = {a1.x, a1.z, b1.x, b1.z, c1.x, c1.z, d1.x, d1.z};
        float py[8] = {a1.y, a1.w, b1.y, b1.w, c1.y, c1.w, d1.y, d1.w};
        int ntri = ni.y - 2;
        float sum = 0.0f;
        #pragma unroll
        for (int t = 0; t < 6; t++) {
            float cross = (px[0] - px[2 + t]) * (py[1 + t] - py[2 + t])
                        - (py[0] - py[2 + t]) * (px[1 + t] - px[2 + t]);
            sum += (t < ntri) ? fabsf(cross) * 0.5f : 0.0f;
        }
        res.y = sum;
    }

    if (i0 + 1 < n) {
        __stcs((float2*)(out + i0), res);
    } else {
        out[i0] = res.x;
    }
}

extern "C" void kernel_launch(void* const* d_in, const int* in_sizes, int n_in,
                              void* d_out, int out_size) {
    const float4* pts = (const float4*)d_in[0];
    const int* num_of_inter = (const int*)d_in[1];
    float* out = (float*)d_out;
    int n = in_sizes[1];

    int threads = 256;
    int rows_per_block = threads * 2;
    int blocks = (n + rows_per_block - 1) / rows_per_block;
    rinter_area_kernel2<<<blocks, threads>>>(pts, num_of_inter, out, n);
}

// round 3
// speedup vs baseline: 1.2966x; 1.2966x over previous
#include <cuda_runtime.h>
#include <cuda_bf16.h>

__global__ __launch_bounds__(256) void rinter_area_kernel3(
    const float4* __restrict__ pts,      // N rows * 4 float4 each
    const int* __restrict__ num_of_inter,
    float* __restrict__ out,
    int n, int half)
{
    int i = blockIdx.x * blockDim.x + threadIdx.x;
    if (i >= half) return;
    int j = i + half;
    bool has_j = (j < n);

    // Two rows, far apart: both loads keep the coalesced 64B-lane-stride
    // geometry. 8 independent LDG.128 front-batched -> MLP ~8.
    const float4* r0 = pts + (size_t)i * 4;
    const float4* r1 = pts + (size_t)j * 4;

    float4 a0 = __ldcs(r0 + 0);
    float4 b0 = __ldcs(r0 + 1);
    float4 c0 = __ldcs(r0 + 2);
    float4 d0 = __ldcs(r0 + 3);
    float4 a1, b1, c1, d1;
    a1 = b1 = c1 = d1 = make_float4(0.f, 0.f, 0.f, 0.f);
    if (has_j) {
        a1 = __ldcs(r1 + 0);
        b1 = __ldcs(r1 + 1);
        c1 = __ldcs(r1 + 2);
        d1 = __ldcs(r1 + 3);
    }
    int n0 = __ldcs(num_of_inter + i);
    int n1 = has_j ? __ldcs(num_of_inter + j) : 0;

    float s0, s1;
    {
        float px[8] = {a0.x, a0.z, b0.x, b0.z, c0.x, c0.z, d0.x, d0.z};
        float py[8] = {a0.y, a0.w, b0.y, b0.w, c0.y, c0.w, d0.y, d0.w};
        int ntri = n0 - 2;
        float sum = 0.0f;
        #pragma unroll
        for (int t = 0; t < 6; t++) {
            float cross = (px[0] - px[2 + t]) * (py[1 + t] - py[2 + t])
                        - (py[0] - py[2 + t]) * (px[1 + t] - px[2 + t]);
            sum += (t < ntri) ? fabsf(cross) * 0.5f : 0.0f;
        }
        s0 = sum;
    }
    {
        float px[8] = {a1.x, a1.z, b1.x, b1.z, c1.x, c1.z, d1.x, d1.z};
        float py[8] = {a1.y, a1.w, b1.y, b1.w, c1.y, c1.w, d1.y, d1.w};
        int ntri = n1 - 2;
        float sum = 0.0f;
        #pragma unroll
        for (int t = 0; t < 6; t++) {
            float cross = (px[0] - px[2 + t]) * (py[1 + t] - py[2 + t])
                        - (py[0] - py[2 + t]) * (px[1 + t] - px[2 + t]);
            sum += (t < ntri) ? fabsf(cross) * 0.5f : 0.0f;
        }
        s1 = sum;
    }

    __stcs(out + i, s0);
    if (has_j) __stcs(out + j, s1);
}

extern "C" void kernel_launch(void* const* d_in, const int* in_sizes, int n_in,
                              void* d_out, int out_size) {
    const float4* pts = (const float4*)d_in[0];
    const int* num_of_inter = (const int*)d_in[1];
    float* out = (float*)d_out;
    int n = in_sizes[1];
    int half = (n + 1) / 2;

    int threads = 256;
    int blocks = (half + threads - 1) / threads;
    rinter_area_kernel3<<<blocks, threads>>>(pts, num_of_inter, out, n, half);
}

// round 4
// speedup vs baseline: 1.3148x; 1.0141x over previous
#include <cuda_runtime.h>
#include <cuda_bf16.h>

__global__ __launch_bounds__(512) void rinter_area_kernel4(
    const float4* __restrict__ pts,      // N rows * 4 float4 each
    const int* __restrict__ num_of_inter,
    float* __restrict__ out,
    int n)
{
    int i = blockIdx.x * blockDim.x + threadIdx.x;
    if (i >= n) return;

    const float4* row = pts + (size_t)i * 4;
    float4 a = __ldcs(row + 0);
    float4 b = __ldcs(row + 1);
    float4 c = __ldcs(row + 2);
    float4 d = __ldcs(row + 3);
    int ntri = __ldcs(num_of_inter + i) - 2;

    float px[8] = {a.x, a.z, b.x, b.z, c.x, c.z, d.x, d.z};
    float py[8] = {a.y, a.w, b.y, b.w, c.y, c.w, d.y, d.w};

    float sum = 0.0f;
    #pragma unroll
    for (int t = 0; t < 6; t++) {
        float cross = (px[0] - px[2 + t]) * (py[1 + t] - py[2 + t])
                    - (py[0] - py[2 + t]) * (px[1 + t] - px[2 + t]);
        sum += (t < ntri) ? fabsf(cross) * 0.5f : 0.0f;
    }
    __stcs(out + i, sum);
}

extern "C" void kernel_launch(void* const* d_in, const int* in_sizes, int n_in,
                              void* d_out, int out_size) {
    const float4* pts = (const float4*)d_in[0];
    const int* num_of_inter = (const int*)d_in[1];
    float* out = (float*)d_out;
    int n = in_sizes[1];

    int threads = 512;
    int blocks = (n + threads - 1) / threads;
    rinter_area_kernel4<<<blocks, threads>>>(pts, num_of_inter, out, n);
}